// round 10
// baseline (speedup 1.0000x reference)
#include <cuda_runtime.h>
#include <math.h>

#define LTOT    19530
#define BB      64
#define SS      32
#define NROWS   2048
#define NBISECT 40
#define N4      4882        // full float4-column groups per row (4*4882 = 19528)
#define NTILE_B 20          // 256-wide float4-group tiles per row
#define P1G     32          // pass-1 blocks per group (one per sample row)
#define BLKG    (P1G + NTILE_B)   // 52 blocks per group
#define NBLK    (BB * BLKG)       // 3328

// Scratch (__device__ globals: allocation-guard compliant)
__device__ float g_pw[NROWS * 8];   // per-row root powers [row][k] = root^k
__device__ int   g_done[BB];        // per-batch pass-1 completion counters

// ---------------------------------------------------------------------------
__global__ void k_init() {
    if (threadIdx.x < BB) g_done[threadIdx.x] = 0;
}

// ---------------------------------------------------------------------------
__device__ __forceinline__ void vec_sq_sum(const float* __restrict__ x,
                                           int lo, int hi, int p,
                                           int tid, float& acc) {
    int a = lo + ((((p - lo) % 4) + 4) % 4);
    if (tid < a - lo) { float v = x[lo + tid]; acc = fmaf(v, v, acc); }
    const int nv = (hi - a) >> 2;
    const float4* __restrict__ xv = (const float4*)(x + a);
    #pragma unroll 4
    for (int i = tid; i < nv; i += 256) {
        float4 v = xv[i];
        acc = fmaf(v.x, v.x, acc);
        acc = fmaf(v.y, v.y, acc);
        acc = fmaf(v.z, v.z, acc);
        acc = fmaf(v.w, v.w, acc);
    }
    const int t0 = a + 4 * nv;
    if (tid < hi - t0) { float v = x[t0 + tid]; acc = fmaf(v, v, acc); }
}

__device__ __forceinline__ int level_of(int idx) {
    if (idx < 5)    return 1;
    if (idx < 30)   return 2;
    if (idx < 155)  return 3;
    if (idx < 780)  return 4;
    if (idx < 3905) return 5;
    return 6;
}

// ---------------------------------------------------------------------------
// Fused kernel: groups of 52 blocks per batch b — 32 pass-1 (row reduce +
// bisection) then 20 pass-2 (scale + mean) that spin until pass-1(b) done.
// Pass-2 reads batch b's 2.5MB while it is still L2-resident.
// ---------------------------------------------------------------------------
__global__ __launch_bounds__(256, 4) void k_main(const float* __restrict__ sig,
                                                 float* __restrict__ out) {
    const int bid = blockIdx.x;
    const int b   = bid / BLKG;
    const int r   = bid - b * BLKG;
    const int tid = threadIdx.x;

    if (r < P1G) {
        // ================= PASS 1: row reduce + bisection =================
        const int row = b * SS + r;
        const float* __restrict__ x = sig + (size_t)row * LTOT;

        float acc[6] = {0.f, 0.f, 0.f, 0.f, 0.f, 0.f};

        const int off[5] = {0, 5, 30, 155, 780};
        #pragma unroll
        for (int k = 0; k < 4; k++)
            for (int i = off[k] + tid; i < off[k + 1]; i += 256) {
                float v = x[i];
                acc[k] = fmaf(v, v, acc[k]);
            }

        const int p = (row & 1) ? 2 : 0;   // row byte base % 16 == 8 for odd rows
        vec_sq_sum(x, 780,  3905, p, tid, acc[4]);
        vec_sq_sum(x, 3905, LTOT, p, tid, acc[5]);

        __shared__ float sm[8][8];
        __shared__ float totals[8];
        const int lane = tid & 31, w = tid >> 5;
        #pragma unroll
        for (int k = 0; k < 6; k++) {
            float v = acc[k];
            #pragma unroll
            for (int o = 16; o > 0; o >>= 1) v += __shfl_down_sync(0xffffffffu, v, o);
            if (lane == 0) sm[w][k] = v;
        }
        __syncthreads();
        if (w == 0) {
            if (lane < 6) {
                float t = 0.f;
                #pragma unroll
                for (int i = 0; i < 8; i++) t += sm[i][lane];
                totals[lane] = t;
            }
            __syncwarp();
            if (lane == 0) {
                float c[7];
                float total = 0.f;
                #pragma unroll
                for (int k = 1; k <= 6; k++) { c[k] = totals[k - 1]; total += c[k]; }
                const float nq  = 1.f + total;
                const float phi = (nq > 4.f) ? (8.f - 16.f / nq) : nq;  // C=4, a=1
                c[0] = 1.f - phi;

                bool fin = true;
                #pragma unroll
                for (int k = 0; k < 7; k++) fin = fin && isfinite(c[k]);

                float lo = 0.f, hi = 2.f;
                #pragma unroll 4
                for (int it = 0; it < NBISECT; it++) {
                    const float mid = 0.5f * (lo + hi);
                    const float u   = mid * mid;
                    float pz = c[6];
                    #pragma unroll
                    for (int k = 5; k >= 0; k--) pz = fmaf(pz, u, c[k]);
                    const bool neg = pz < 0.f;
                    lo = neg ? mid : lo;
                    hi = neg ? hi  : mid;
                }
                float root = 0.5f * (lo + hi);
                if (!fin) root = 0.f;
                root = fminf(root, 1.f);

                float pw = 1.f;
                g_pw[row * 8 + 0] = 1.f;
                #pragma unroll
                for (int k = 1; k <= 6; k++) { pw *= root; g_pw[row * 8 + k] = pw; }
                g_pw[row * 8 + 7] = 0.f;

                __threadfence();                 // publish g_pw before counter
                atomicAdd(&g_done[b], 1);
            }
        }
    } else {
        // ================= PASS 2: scale + mean over S ====================
        const int tt = r - P1G;

        if (tid == 0) {
            while (atomicAdd(&g_done[b], 0) < P1G) __nanosleep(128);
        }
        __syncthreads();
        __threadfence();                         // acquire g_pw writes

        __shared__ float spw[SS * 8];
        __shared__ float sh[4 * 256 + 4];        // shifted odd-row sums

        spw[tid] = g_pw[(size_t)b * SS * 8 + tid];
        __syncthreads();

        const int j4 = tt * 256 + tid;
        const int e0 = 4 * j4;
        const bool full = (j4 < N4);
        const bool tail = (j4 == N4);

        const float* __restrict__ base = sig + (size_t)b * SS * LTOT;
        const float inv = 1.f / (float)SS;

        float a0 = 0.f, a1 = 0.f, a2 = 0.f, a3 = 0.f;   // cols e0..e0+3
        float c0 = 0.f, c1 = 0.f, c2 = 0.f, c3 = 0.f;   // odd rows, cols e0+2..e0+5
        float h0 = 0.f, h1 = 0.f;                       // halo: first 2 cols, odd rows

        if (full) {
            const int lv0 = level_of(e0);
            const int lv1 = level_of(e0 + 1);
            const int lv2 = level_of(e0 + 2);
            const int lv3 = level_of(e0 + 3);
            const int lv4 = level_of(e0 + 4);
            const int lv5 = level_of(e0 + 5);

            #pragma unroll
            for (int sb = 0; sb < SS; sb += 8) {
                float4 ue[4], uo[4];
                #pragma unroll
                for (int t = 0; t < 4; t++)
                    ue[t] = *(const float4*)(base + (size_t)(sb + 2 * t) * LTOT + e0);
                #pragma unroll
                for (int t = 0; t < 4; t++)
                    uo[t] = *(const float4*)(base + (size_t)(sb + 2 * t + 1) * LTOT + e0 + 2);
                #pragma unroll
                for (int t = 0; t < 4; t++) {
                    const int se = sb + 2 * t, so = se + 1;
                    a0 = fmaf(ue[t].x, spw[se * 8 + lv0], a0);
                    a1 = fmaf(ue[t].y, spw[se * 8 + lv1], a1);
                    a2 = fmaf(ue[t].z, spw[se * 8 + lv2], a2);
                    a3 = fmaf(ue[t].w, spw[se * 8 + lv3], a3);
                    c0 = fmaf(uo[t].x, spw[so * 8 + lv2], c0);
                    c1 = fmaf(uo[t].y, spw[so * 8 + lv3], c1);
                    c2 = fmaf(uo[t].z, spw[so * 8 + lv4], c2);
                    c3 = fmaf(uo[t].w, spw[so * 8 + lv5], c3);
                }
            }
            if (tid == 0) {
                #pragma unroll
                for (int s = 1; s < SS; s += 2) {
                    const float2 v = *(const float2*)(base + (size_t)s * LTOT + e0);
                    h0 = fmaf(v.x, spw[s * 8 + lv0], h0);
                    h1 = fmaf(v.y, spw[s * 8 + lv1], h1);
                }
            }
        } else if (tail) {
            // cols 19528/19529 (level 6): EVEN rows only; odd via shift-add
            #pragma unroll
            for (int s = 0; s < SS; s += 2) {
                const float2 v = *(const float2*)(base + (size_t)s * LTOT + e0);
                const float  w6 = spw[s * 8 + 6];
                a0 = fmaf(v.x, w6, a0);
                a1 = fmaf(v.y, w6, a1);
            }
        }

        if (tid == 0) { sh[0] = h0; sh[1] = h1; }
        sh[4 * tid + 2] = full ? c0 : 0.f;
        sh[4 * tid + 3] = full ? c1 : 0.f;
        sh[4 * tid + 4] = full ? c2 : 0.f;
        sh[4 * tid + 5] = full ? c3 : 0.f;
        __syncthreads();

        if (full) {
            float* o = out + (size_t)b * LTOT + e0;
            *(float2*)o       = make_float2((a0 + sh[4 * tid])     * inv,
                                            (a1 + sh[4 * tid + 1]) * inv);
            *(float2*)(o + 2) = make_float2((a2 + sh[4 * tid + 2]) * inv,
                                            (a3 + sh[4 * tid + 3]) * inv);
        } else if (tail) {
            float* o = out + (size_t)b * LTOT + e0;
            *(float2*)o = make_float2((a0 + sh[4 * tid])     * inv,
                                      (a1 + sh[4 * tid + 1]) * inv);
        }
    }
}

// ---------------------------------------------------------------------------
extern "C" void kernel_launch(void* const* d_in, const int* in_sizes, int n_in,
                              void* d_out, int out_size) {
    const float* sig = (const float*)d_in[0];
    float* out = (float*)d_out;

    k_init<<<1, 64>>>();
    k_main<<<NBLK, 256>>>(sig, out);
}

// round 11
// speedup vs baseline: 1.1626x; 1.1626x over previous
#include <cuda_runtime.h>
#include <math.h>

#define LTOT    19530
#define BB      64
#define SS      32
#define NROWS   2048
#define NBISECT 40
#define N4      4882        // full float4-column groups per row (4*4882 = 19528)
#define NTILE_B 20          // 256-wide float4-group tiles per row
#define P1G     32          // pass-1 blocks per batch
#define LAG     8           // batches of pipeline lag between p1(b) and p2(b)
#define NBLK    (BB * (P1G + NTILE_B))   // 3328
// bid regions
#define REG_A   (P1G * LAG)                       // 256
#define REG_B   (REG_A + (P1G + NTILE_B) * (BB - LAG))  // 3168

// Scratch (__device__ globals: allocation-guard compliant)
__device__ float g_pw[NROWS * 8];   // per-row root powers [row][k] = root^k
__device__ int   g_done[BB];        // per-batch pass-1 completion counters

// ---------------------------------------------------------------------------
__global__ void k_init() {
    if (threadIdx.x < BB) g_done[threadIdx.x] = 0;
}

// ---------------------------------------------------------------------------
__device__ __forceinline__ void vec_sq_sum(const float* __restrict__ x,
                                           int lo, int hi, int p,
                                           int tid, float& acc) {
    int a = lo + ((((p - lo) % 4) + 4) % 4);
    if (tid < a - lo) { float v = x[lo + tid]; acc = fmaf(v, v, acc); }
    const int nv = (hi - a) >> 2;
    const float4* __restrict__ xv = (const float4*)(x + a);
    #pragma unroll 4
    for (int i = tid; i < nv; i += 256) {
        float4 v = xv[i];
        acc = fmaf(v.x, v.x, acc);
        acc = fmaf(v.y, v.y, acc);
        acc = fmaf(v.z, v.z, acc);
        acc = fmaf(v.w, v.w, acc);
    }
    const int t0 = a + 4 * nv;
    if (tid < hi - t0) { float v = x[t0 + tid]; acc = fmaf(v, v, acc); }
}

__device__ __forceinline__ int level_of(int idx) {
    if (idx < 5)    return 1;
    if (idx < 30)   return 2;
    if (idx < 155)  return 3;
    if (idx < 780)  return 4;
    if (idx < 3905) return 5;
    return 6;
}

// ---------------------------------------------------------------------------
__device__ __forceinline__ void pass1(const float* __restrict__ sig, int row, int tid) {
    const float* __restrict__ x = sig + (size_t)row * LTOT;

    float acc[6] = {0.f, 0.f, 0.f, 0.f, 0.f, 0.f};

    const int off[5] = {0, 5, 30, 155, 780};
    #pragma unroll
    for (int k = 0; k < 4; k++)
        for (int i = off[k] + tid; i < off[k + 1]; i += 256) {
            float v = x[i];
            acc[k] = fmaf(v, v, acc[k]);
        }

    const int p = (row & 1) ? 2 : 0;   // row byte base % 16 == 8 for odd rows
    vec_sq_sum(x, 780,  3905, p, tid, acc[4]);
    vec_sq_sum(x, 3905, LTOT, p, tid, acc[5]);

    __shared__ float sm[8][8];
    __shared__ float totals[8];
    const int lane = tid & 31, w = tid >> 5;
    #pragma unroll
    for (int k = 0; k < 6; k++) {
        float v = acc[k];
        #pragma unroll
        for (int o = 16; o > 0; o >>= 1) v += __shfl_down_sync(0xffffffffu, v, o);
        if (lane == 0) sm[w][k] = v;
    }
    __syncthreads();
    if (w == 0) {
        if (lane < 6) {
            float t = 0.f;
            #pragma unroll
            for (int i = 0; i < 8; i++) t += sm[i][lane];
            totals[lane] = t;
        }
        __syncwarp();
        if (lane == 0) {
            float c[7];
            float total = 0.f;
            #pragma unroll
            for (int k = 1; k <= 6; k++) { c[k] = totals[k - 1]; total += c[k]; }
            const float nq  = 1.f + total;
            const float phi = (nq > 4.f) ? (8.f - 16.f / nq) : nq;  // C=4, a=1
            c[0] = 1.f - phi;

            bool fin = true;
            #pragma unroll
            for (int k = 0; k < 7; k++) fin = fin && isfinite(c[k]);

            float lo = 0.f, hi = 2.f;
            #pragma unroll 4
            for (int it = 0; it < NBISECT; it++) {
                const float mid = 0.5f * (lo + hi);
                const float u   = mid * mid;
                float pz = c[6];
                #pragma unroll
                for (int k = 5; k >= 0; k--) pz = fmaf(pz, u, c[k]);
                const bool neg = pz < 0.f;
                lo = neg ? mid : lo;
                hi = neg ? hi  : mid;
            }
            float root = 0.5f * (lo + hi);
            if (!fin) root = 0.f;
            root = fminf(root, 1.f);

            float pw = 1.f;
            g_pw[row * 8 + 0] = 1.f;
            #pragma unroll
            for (int k = 1; k <= 6; k++) { pw *= root; g_pw[row * 8 + k] = pw; }
            g_pw[row * 8 + 7] = 0.f;

            __threadfence();                 // publish g_pw before counter
            atomicAdd(&g_done[row >> 5], 1);
        }
    }
}

__device__ __forceinline__ void pass2(const float* __restrict__ sig,
                                      float* __restrict__ out,
                                      int b, int tt, int tid) {
    if (tid == 0) {
        while (atomicAdd(&g_done[b], 0) < P1G) __nanosleep(256);
    }
    __syncthreads();
    __threadfence();                         // acquire g_pw writes

    __shared__ float spw[SS * 8];
    __shared__ float sh[4 * 256 + 4];        // shifted odd-row sums

    spw[tid] = g_pw[(size_t)b * SS * 8 + tid];
    __syncthreads();

    const int j4 = tt * 256 + tid;
    const int e0 = 4 * j4;
    const bool full = (j4 < N4);
    const bool tail = (j4 == N4);

    const float* __restrict__ base = sig + (size_t)b * SS * LTOT;
    const float inv = 1.f / (float)SS;

    float a0 = 0.f, a1 = 0.f, a2 = 0.f, a3 = 0.f;   // cols e0..e0+3
    float c0 = 0.f, c1 = 0.f, c2 = 0.f, c3 = 0.f;   // odd rows, cols e0+2..e0+5
    float h0 = 0.f, h1 = 0.f;                       // halo: first 2 cols, odd rows

    if (full) {
        const int lv0 = level_of(e0);
        const int lv1 = level_of(e0 + 1);
        const int lv2 = level_of(e0 + 2);
        const int lv3 = level_of(e0 + 3);
        const int lv4 = level_of(e0 + 4);
        const int lv5 = level_of(e0 + 5);

        #pragma unroll
        for (int sb = 0; sb < SS; sb += 8) {
            float4 ue[4], uo[4];
            #pragma unroll
            for (int t = 0; t < 4; t++)
                ue[t] = *(const float4*)(base + (size_t)(sb + 2 * t) * LTOT + e0);
            #pragma unroll
            for (int t = 0; t < 4; t++)
                uo[t] = *(const float4*)(base + (size_t)(sb + 2 * t + 1) * LTOT + e0 + 2);
            #pragma unroll
            for (int t = 0; t < 4; t++) {
                const int se = sb + 2 * t, so = se + 1;
                a0 = fmaf(ue[t].x, spw[se * 8 + lv0], a0);
                a1 = fmaf(ue[t].y, spw[se * 8 + lv1], a1);
                a2 = fmaf(ue[t].z, spw[se * 8 + lv2], a2);
                a3 = fmaf(ue[t].w, spw[se * 8 + lv3], a3);
                c0 = fmaf(uo[t].x, spw[so * 8 + lv2], c0);
                c1 = fmaf(uo[t].y, spw[so * 8 + lv3], c1);
                c2 = fmaf(uo[t].z, spw[so * 8 + lv4], c2);
                c3 = fmaf(uo[t].w, spw[so * 8 + lv5], c3);
            }
        }
        if (tid == 0) {
            #pragma unroll
            for (int s = 1; s < SS; s += 2) {
                const float2 v = *(const float2*)(base + (size_t)s * LTOT + e0);
                h0 = fmaf(v.x, spw[s * 8 + lv0], h0);
                h1 = fmaf(v.y, spw[s * 8 + lv1], h1);
            }
        }
    } else if (tail) {
        // cols 19528/19529 (level 6): EVEN rows only; odd via shift-add
        #pragma unroll
        for (int s = 0; s < SS; s += 2) {
            const float2 v = *(const float2*)(base + (size_t)s * LTOT + e0);
            const float  w6 = spw[s * 8 + 6];
            a0 = fmaf(v.x, w6, a0);
            a1 = fmaf(v.y, w6, a1);
        }
    }

    if (tid == 0) { sh[0] = h0; sh[1] = h1; }
    sh[4 * tid + 2] = full ? c0 : 0.f;
    sh[4 * tid + 3] = full ? c1 : 0.f;
    sh[4 * tid + 4] = full ? c2 : 0.f;
    sh[4 * tid + 5] = full ? c3 : 0.f;
    __syncthreads();

    if (full) {
        float* o = out + (size_t)b * LTOT + e0;
        *(float2*)o       = make_float2((a0 + sh[4 * tid])     * inv,
                                        (a1 + sh[4 * tid + 1]) * inv);
        *(float2*)(o + 2) = make_float2((a2 + sh[4 * tid + 2]) * inv,
                                        (a3 + sh[4 * tid + 3]) * inv);
    } else if (tail) {
        float* o = out + (size_t)b * LTOT + e0;
        *(float2*)o = make_float2((a0 + sh[4 * tid])     * inv,
                                  (a1 + sh[4 * tid + 1]) * inv);
    }
}

// ---------------------------------------------------------------------------
// Fused pipelined kernel. bid layout (monotonic dispatch => no deadlock):
//   [0, 256):       p1 for batches 0..7
//   [256, 3168):    groups g=8..63: 32 x p1(g) then 20 x p2(g-8)
//   [3168, 3328):   p2 for batches 56..63
// p2(b) trails p1(b) by >= 385 bids (~>half a wave) so spin is ~never taken.
// ---------------------------------------------------------------------------
__global__ __launch_bounds__(256, 4) void k_main(const float* __restrict__ sig,
                                                 float* __restrict__ out) {
    const int bid = blockIdx.x;
    const int tid = threadIdx.x;

    if (bid < REG_A) {
        pass1(sig, (bid >> 5) * SS + (bid & 31), tid);
    } else if (bid < REG_B) {
        const int t = bid - REG_A;
        const int g = LAG + t / (P1G + NTILE_B);
        const int r = t % (P1G + NTILE_B);
        if (r < P1G) pass1(sig, g * SS + r, tid);
        else         pass2(sig, out, g - LAG, r - P1G, tid);
    } else {
        const int t = bid - REG_B;
        pass2(sig, out, (BB - LAG) + t / NTILE_B, t % NTILE_B, tid);
    }
}

// ---------------------------------------------------------------------------
extern "C" void kernel_launch(void* const* d_in, const int* in_sizes, int n_in,
                              void* d_out, int out_size) {
    const float* sig = (const float*)d_in[0];
    float* out = (float*)d_out;

    k_init<<<1, 64>>>();
    k_main<<<NBLK, 256>>>(sig, out);
}